// round 3
// baseline (speedup 1.0000x reference)
#include <cuda_runtime.h>
#include <math.h>

#define NN 16384
#define EE 262144
typedef unsigned long long ull;

__device__ float g_ns  [NN * 120];
__device__ float g_ne  [NN * 240];
__device__ float g_qinv[NN * 120];
__device__ float g_kinv[NN * 120];
__device__ float g_vinv[NN * 120];
__device__ float g_qsph[NN * 120];
__device__ float g_ksph[NN * 120];
__device__ float g_vsph[NN * 112];
__device__ float g_d   [(size_t)EE * 112];
__device__ float g_h   [(size_t)EE * 240];
__device__ float g_w   [(size_t)EE * 120];

__device__ __forceinline__ ull pack2(float x, float y){ ull r; asm("mov.b64 %0,{%1,%2};":"=l"(r):"f"(x),"f"(y)); return r; }
__device__ __forceinline__ void unpack2(ull v, float&x, float&y){ asm("mov.b64 {%0,%1},%2;":"=f"(x),"=f"(y):"l"(v)); }
__device__ __forceinline__ void fma2(ull&d, ull a, ull b){ asm("fma.rn.f32x2 %0,%1,%2,%0;":"+l"(d):"l"(a),"l"(b)); }
__device__ __forceinline__ float4 ldg4(const float* p){ return __ldg(reinterpret_cast<const float4*>(p)); }
__device__ __forceinline__ void red4(float* p, float a, float b, float c, float d){
    asm volatile("red.global.add.v4.f32 [%0],{%1,%2,%3,%4};"::"l"(p),"f"(a),"f"(b),"f"(c),"f"(d):"memory");
}
__device__ __forceinline__ float wsum(float v){
    #pragma unroll
    for (int o=16;o;o>>=1) v += __shfl_xor_sync(0xffffffffu, v, o);
    return v;
}

// ---------- K0: init output with residual ----------
__global__ void init_out_kernel(const float* __restrict__ xs, const float* __restrict__ xe, float* __restrict__ out){
    size_t i = (size_t)blockIdx.x*blockDim.x + threadIdx.x;
    size_t ns = (size_t)NN*120, ne = (size_t)NN*240;
    if (i < ns) out[i] = xs[i];
    if (i < ne) out[ns + i] = xe[i];
}

// ---------- K1: node LayerNorm + O3 LayerNorm (warp/node) ----------
__global__ void node_norm_kernel(const float* __restrict__ xs_in, const float* __restrict__ xe_in,
                                 const float* __restrict__ lnw, const float* __restrict__ lnb,
                                 const float* __restrict__ o3w){
    int lane = threadIdx.x & 31;
    int node = blockIdx.x*4 + (threadIdx.x >> 5);
    if (node >= NN) return;
    const float* xs = xs_in + (size_t)node*120;
    float v0=xs[lane], v1=xs[lane+32], v2=xs[lane+64], v3=(lane<24)?xs[lane+96]:0.f;
    float s = wsum(v0+v1+v2+v3);
    float q = wsum(v0*v0+v1*v1+v2*v2+v3*v3);
    float mean = s*(1.f/120.f);
    float inv = rsqrtf(q*(1.f/120.f) - mean*mean + 1e-5f);
    float* ns = g_ns + (size_t)node*120;
    ns[lane]    = (v0-mean)*inv*__ldg(lnw+lane)    + __ldg(lnb+lane);
    ns[lane+32] = (v1-mean)*inv*__ldg(lnw+lane+32) + __ldg(lnb+lane+32);
    ns[lane+64] = (v2-mean)*inv*__ldg(lnw+lane+64) + __ldg(lnb+lane+64);
    if (lane<24) ns[lane+96] = (v3-mean)*inv*__ldg(lnw+lane+96) + __ldg(lnb+lane+96);

    const float* xe = xe_in + (size_t)node*240;
    float* ne = g_ne + (size_t)node*240;
    { // l=0: 64 comps, mean-center over mul, rms over 64
        float e0=xe[lane], e1=xe[lane+32];
        float m = wsum(e0+e1)*(1.f/64.f);
        float c0=e0-m, c1=e1-m;
        float r = rsqrtf(wsum(c0*c0+c1*c1)*(1.f/64.f) + 1e-5f);
        ne[lane]    = c0*r*__ldg(o3w+lane);
        ne[lane+32] = c1*r*__ldg(o3w+lane+32);
    }
    { // l=1: comps 64..159, rms over 96
        float y0=xe[64+lane], y1=xe[96+lane], y2=xe[128+lane];
        float r = rsqrtf(wsum(y0*y0+y1*y1+y2*y2)*(1.f/96.f) + 1e-5f);
        ne[64+lane]  = y0*r*__ldg(o3w+64+(lane)/3);
        ne[96+lane]  = y1*r*__ldg(o3w+64+(32+lane)/3);
        ne[128+lane] = y2*r*__ldg(o3w+64+(64+lane)/3);
    }
    { // l=2: comps 160..239, rms over 80
        float z0=xe[160+lane], z1=xe[192+lane], z2=(lane<16)?xe[224+lane]:0.f;
        float r = rsqrtf(wsum(z0*z0+z1*z1+z2*z2)*(1.f/80.f) + 1e-5f);
        ne[160+lane] = z0*r*__ldg(o3w+96+(lane)/5);
        ne[192+lane] = z1*r*__ldg(o3w+96+(32+lane)/5);
        if (lane<16) ne[224+lane] = z2*r*__ldg(o3w+96+(64+lane)/5);
    }
}

// ---------- generic GEMM: C[:,colOff+j] = op(A@[B1;B2] + b1 + b2) * rowScale ----------
__global__ __launch_bounds__(256) void gemm_kernel(
    const float* __restrict__ A, int lda,
    const float* __restrict__ B1, const float* __restrict__ B2, int kdim, int k1,
    const float* __restrict__ bias1, const float* __restrict__ bias2,
    const float* __restrict__ rowScale,
    float* __restrict__ C, int ldc, int colOff, int ncols, int fuseSilu)
{
    __shared__ alignas(16) float Bsh[32*128];
    __shared__ alignas(16) float Ash[32*132];
    __shared__ float sb[128];
    int tid = threadIdx.x;
    if (tid < 128){
        float v = 0.f;
        if (tid < ncols){ if (bias1) v = __ldg(bias1+tid); if (bias2) v += __ldg(bias2+tid); }
        sb[tid] = v;
    }
    int ct = tid>>5, rt = tid&31;
    int rowBase = blockIdx.x*128, colBase = ct*16;
    ull acc[4][8];
    #pragma unroll
    for (int r=0;r<4;r++){
        #pragma unroll
        for (int j=0;j<8;j++) acc[r][j]=0ull;
    }
    for (int kc=0; kc<kdim; kc+=32){
        int klen = min(32, kdim-kc);
        __syncthreads();
        for (int idx=tid; idx<klen*128; idx+=256){
            int k = idx>>7, j = idx&127, kg = kc+k;
            float v = 0.f;
            if (j<ncols) v = (kg<k1)? __ldg(B1+kg*ncols+j) : __ldg(B2+(kg-k1)*ncols+j);
            Bsh[idx] = v;
        }
        if (klen==32){
            for (int idx=tid; idx<128*32; idx+=256){
                int row=idx>>5, kk=idx&31;
                Ash[kk*132+row] = A[(size_t)(rowBase+row)*lda + kc+kk];
            }
        } else {
            for (int idx=tid; idx<128*klen; idx+=256){
                int row=idx/klen, kk=idx-row*klen;
                Ash[kk*132+row] = A[(size_t)(rowBase+row)*lda + kc+kk];
            }
        }
        __syncthreads();
        #pragma unroll 4
        for (int k=0;k<klen;k++){
            float4 a4 = *reinterpret_cast<const float4*>(&Ash[k*132 + (rt<<2)]);
            ull ap0=pack2(a4.x,a4.x), ap1=pack2(a4.y,a4.y), ap2=pack2(a4.z,a4.z), ap3=pack2(a4.w,a4.w);
            const ulonglong2* bp = reinterpret_cast<const ulonglong2*>(&Bsh[k*128 + colBase]);
            ulonglong2 b01=bp[0], b23=bp[1], b45=bp[2], b67=bp[3];
            ull bb[8] = {b01.x,b01.y,b23.x,b23.y,b45.x,b45.y,b67.x,b67.y};
            #pragma unroll
            for (int j=0;j<8;j++){
                fma2(acc[0][j],ap0,bb[j]); fma2(acc[1][j],ap1,bb[j]);
                fma2(acc[2][j],ap2,bb[j]); fma2(acc[3][j],ap3,bb[j]);
            }
        }
    }
    #pragma unroll
    for (int r=0;r<4;r++){
        int row = rowBase + rt*4 + r;
        float sc = rowScale ? __ldg(rowScale+row) : 1.f;
        #pragma unroll
        for (int j=0;j<8;j++){
            float lo,hi; unpack2(acc[r][j],lo,hi);
            int c0 = colBase + 2*j;
            float x0 = lo + sb[c0], x1 = hi + sb[c0+1];
            if (fuseSilu){ x0 = x0/(1.f+__expf(-x0)); x1 = x1/(1.f+__expf(-x1)); }
            x0 *= sc; x1 *= sc;
            if (c0   < ncols) C[(size_t)row*ldc + colOff + c0]   = x0;
            if (c0+1 < ncols) C[(size_t)row*ldc + colOff + c0+1] = x1;
        }
    }
}

// ---------- K3: d[e,112] = equi_dot(ne[nb] - ne[ct]) ----------
__global__ __launch_bounds__(128) void equi_dot_kernel(const int* __restrict__ ei){
    int e = blockIdx.x;
    int t = threadIdx.x;
    if (t >= 112) return;
    int ct = __ldg(ei+e), nb = __ldg(ei+EE+e);
    const float* a = g_ne + (size_t)nb*240;
    const float* b = g_ne + (size_t)ct*240;
    float out;
    if (t < 64){
        float d = __ldg(a+t) - __ldg(b+t);
        out = d*d;
    } else if (t < 96){
        int base = 64 + (t-64)*3;
        out = 0.f;
        #pragma unroll
        for (int j=0;j<3;j++){ float d = __ldg(a+base+j) - __ldg(b+base+j); out += d*d; }
    } else {
        int base = 160 + (t-96)*5;
        out = 0.f;
        #pragma unroll
        for (int j=0;j<5;j++){ float d = __ldg(a+base+j) - __ldg(b+base+j); out += d*d; }
    }
    g_d[(size_t)e*112 + t] = out;
}

// ---------- K6: attention + gated messages + scatter ----------
__global__ __launch_bounds__(256) void edge_attn_kernel(const int* __restrict__ ei,
                                                        const float* __restrict__ fcut,
                                                        const float* __restrict__ rsh,
                                                        float* __restrict__ outS,
                                                        float* __restrict__ outE){
    __shared__ float sgate[8][116];
    int warp = threadIdx.x>>5, lane = threadIdx.x&31;
    int e = blockIdx.x*8 + warp;
    int ct = __ldg(ei+e), nb = __ldg(ei+EE+e);
    float fc = __ldg(fcut+e);
    const float* w  = g_w   + (size_t)e*120;
    const float* qi = g_qinv + (size_t)ct*120;
    const float* ki = g_kinv + (size_t)nb*120;
    const float* vi = g_vinv + (size_t)nb*120;
    const float* qs = g_qsph + (size_t)ct*120;
    const float* ks = g_ksph + (size_t)nb*120;
    const float* vs = g_vsph + (size_t)nb*112;

    float s0=0,s1=0,s2=0,s3=0,t0=0,t1=0,t2=0;
    if (lane < 30){
        float4 wv = ldg4(w + 4*lane);
        float4 q  = ldg4(qi + 4*lane), k = ldg4(ki + 4*lane);
        float4 qe = ldg4(qs + 4*lane), ke = ldg4(ks + 4*lane);
        float wa[4]={wv.x,wv.y,wv.z,wv.w};
        float pa[4]={q.x*k.x, q.y*k.y, q.z*k.z, q.w*k.w};
        float pe[4]={qe.x*ke.x, qe.y*ke.y, qe.z*ke.z, qe.w*ke.w};
        #pragma unroll
        for (int j=0;j<4;j++){
            int idx = 4*lane + j;
            float p = wa[j]*pa[j];
            float pq = wa[j]*pe[j];
            int h = idx/30, l = idx/40;
            s0 += (h==0)?p:0.f; s1 += (h==1)?p:0.f; s2 += (h==2)?p:0.f; s3 += (h==3)?p:0.f;
            t0 += (l==0)?pq:0.f; t1 += (l==1)?pq:0.f; t2 += (l==2)?pq:0.f;
        }
    }
    const float SC_S = 0.091287092917527686f;   // 1/sqrt(120)
    const float SC_E = 0.094491118252306805f;   // 1/sqrt(112)
    s0 = wsum(s0)*SC_S; s1 = wsum(s1)*SC_S; s2 = wsum(s2)*SC_S; s3 = wsum(s3)*SC_S;
    t0 = wsum(t0)*SC_E; t1 = wsum(t1)*SC_E; t2 = wsum(t2)*SC_E;

    if (lane < 30){
        float4 v = ldg4(vi + 4*lane);
        float va[4]={v.x,v.y,v.z,v.w}, m[4];
        #pragma unroll
        for (int j=0;j<4;j++){
            int h = (4*lane+j)/30;
            float ss = (h==0)?s0:((h==1)?s1:((h==2)?s2:s3));
            m[j] = ss*va[j];
        }
        red4(outS + (size_t)ct*120 + 4*lane, m[0],m[1],m[2],m[3]);
    }
    if (lane < 28){
        float4 v = ldg4(vs + 4*lane);
        float va[4]={v.x,v.y,v.z,v.w};
        #pragma unroll
        for (int j=0;j<4;j++){
            int ir = 4*lane + j;
            float tl = (ir<64)?t0:((ir<96)?t1:t2);
            sgate[warp][ir] = tl*va[j]*fc;
        }
    }
    __syncwarp();
    if (lane < 30){
        int base = 8*lane;
        float4 r0 = ldg4(rsh + (size_t)e*240 + base);
        float4 r1 = ldg4(rsh + (size_t)e*240 + base + 4);
        float ra[8]={r0.x,r0.y,r0.z,r0.w,r1.x,r1.y,r1.z,r1.w}, m[8];
        #pragma unroll
        for (int j=0;j<8;j++){
            int c = base + j;
            int ir = (c<64)? c : (c<160)? 64+(c-64)/3 : 96+(c-160)/5;
            m[j] = ra[j]*sgate[warp][ir];
        }
        red4(outE + (size_t)ct*240 + base,     m[0],m[1],m[2],m[3]);
        red4(outE + (size_t)ct*240 + base + 4, m[4],m[5],m[6],m[7]);
    }
}

extern "C" void kernel_launch(void* const* d_in, const int* in_sizes, int n_in,
                              void* d_out, int out_size){
    const float* node_scalar=(const float*)d_in[0];
    const float* node_equi  =(const float*)d_in[1];
    const float* rbf        =(const float*)d_in[2];
    const float* fcut       =(const float*)d_in[3];
    const float* rsh        =(const float*)d_in[4];
    const float* ln_w =(const float*)d_in[5];
    const float* ln_b =(const float*)d_in[6];
    const float* o3w  =(const float*)d_in[7];
    const float* Wq   =(const float*)d_in[8];
    const float* Wk   =(const float*)d_in[9];
    const float* Wv   =(const float*)d_in[10];
    const float* Wqs  =(const float*)d_in[11];
    const float* Wks  =(const float*)d_in[12];
    const float* Wvs  =(const float*)d_in[13];
    const float* rbf_w1=(const float*)d_in[14];
    const float* rbf_b1=(const float*)d_in[15];
    const float* rbf_w2=(const float*)d_in[16];
    const float* rbf_b2=(const float*)d_in[17];
    const float* inv_w1=(const float*)d_in[18];
    const float* inv_b1=(const float*)d_in[19];
    const float* inv_w2=(const float*)d_in[20];
    const float* inv_b2=(const float*)d_in[21];
    const int*   ei    =(const int*)d_in[22];

    float* outS = (float*)d_out;
    float* outE = outS + (size_t)NN*120;

    float *ns_p, *qi_p, *ki_p, *vi_p, *qs_p, *ks_p, *vs_p, *d_p, *h_p, *w_p;
    cudaGetSymbolAddress((void**)&ns_p, g_ns);
    cudaGetSymbolAddress((void**)&qi_p, g_qinv);
    cudaGetSymbolAddress((void**)&ki_p, g_kinv);
    cudaGetSymbolAddress((void**)&vi_p, g_vinv);
    cudaGetSymbolAddress((void**)&qs_p, g_qsph);
    cudaGetSymbolAddress((void**)&ks_p, g_ksph);
    cudaGetSymbolAddress((void**)&vs_p, g_vsph);
    cudaGetSymbolAddress((void**)&d_p,  g_d);
    cudaGetSymbolAddress((void**)&h_p,  g_h);
    cudaGetSymbolAddress((void**)&w_p,  g_w);

    // K0: residual init
    init_out_kernel<<<(NN*240 + 255)/256, 256>>>(node_scalar, node_equi, (float*)d_out);
    // K1: norms
    node_norm_kernel<<<NN/4, 128>>>(node_scalar, node_equi, ln_w, ln_b, o3w);
    // K2: projections
    gemm_kernel<<<NN/128,256>>>(ns_p,120, Wq, nullptr,120,120, nullptr,nullptr,nullptr, qi_p,120,0,120,0);
    gemm_kernel<<<NN/128,256>>>(ns_p,120, Wk, nullptr,120,120, nullptr,nullptr,nullptr, ki_p,120,0,120,0);
    gemm_kernel<<<NN/128,256>>>(ns_p,120, Wv, nullptr,120,120, nullptr,nullptr,nullptr, vi_p,120,0,120,0);
    gemm_kernel<<<NN/128,256>>>(ns_p,120, Wqs,nullptr,120,120, nullptr,nullptr,nullptr, qs_p,120,0,120,0);
    gemm_kernel<<<NN/128,256>>>(ns_p,120, Wks,nullptr,120,120, nullptr,nullptr,nullptr, ks_p,120,0,120,0);
    gemm_kernel<<<NN/128,256>>>(ns_p,120, Wvs,nullptr,120,120, nullptr,nullptr,nullptr, vs_p,112,0,112,0);
    // K3: edge invariants
    equi_dot_kernel<<<EE,128>>>(ei);
    // K4: hidden activations into concat buffer
    gemm_kernel<<<EE/128,256>>>(d_p,112, inv_w1,nullptr,112,112, inv_b1,nullptr,nullptr, h_p,240,0,  120,1);
    gemm_kernel<<<EE/128,256>>>(rbf,20,  rbf_w1,nullptr,20,20,   rbf_b1,nullptr,nullptr, h_p,240,120,120,1);
    // K5: w = (h @ [inv_w2; rbf_w2] + b2a + b2b) * fcut
    gemm_kernel<<<EE/128,256>>>(h_p,240, inv_w2,rbf_w2,240,120,  inv_b2,rbf_b2, fcut,    w_p,120,0,  120,0);
    // K6: attention + scatter
    edge_attn_kernel<<<EE/8,256>>>(ei, fcut, rsh, outS, outE);
}

// round 4
// speedup vs baseline: 1.4056x; 1.4056x over previous
#include <cuda_runtime.h>
#include <math.h>

#define NN 16384
#define EE 262144
typedef unsigned long long ull;

__device__ float g_ns  [NN * 120];
__device__ float g_ne  [NN * 240];
__device__ float g_qinv[NN * 120];
__device__ float g_kinv[NN * 120];
__device__ float g_vinv[NN * 120];
__device__ float g_qsph[NN * 120];
__device__ float g_ksph[NN * 120];
__device__ float g_vsph[NN * 112];
__device__ float g_w   [(size_t)EE * 120];

__device__ __forceinline__ ull pack2(float x, float y){ ull r; asm("mov.b64 %0,{%1,%2};":"=l"(r):"f"(x),"f"(y)); return r; }
__device__ __forceinline__ void unpack2(ull v, float&x, float&y){ asm("mov.b64 {%0,%1},%2;":"=f"(x),"=f"(y):"l"(v)); }
__device__ __forceinline__ void fma2(ull&d, ull a, ull b){ asm("fma.rn.f32x2 %0,%1,%2,%0;":"+l"(d):"l"(a),"l"(b)); }
__device__ __forceinline__ float4 ldg4(const float* p){ return __ldg(reinterpret_cast<const float4*>(p)); }
__device__ __forceinline__ void red4(float* p, float a, float b, float c, float d){
    asm volatile("red.global.add.v4.f32 [%0],{%1,%2,%3,%4};"::"l"(p),"f"(a),"f"(b),"f"(c),"f"(d):"memory");
}
__device__ __forceinline__ float wsum(float v){
    #pragma unroll
    for (int o=16;o;o>>=1) v += __shfl_xor_sync(0xffffffffu, v, o);
    return v;
}
__device__ __forceinline__ unsigned smem_u32(const void* p){
    unsigned a; asm("{ .reg .u64 t; cvta.to.shared.u64 t, %1; cvt.u32.u64 %0, t; }":"=r"(a):"l"(p)); return a;
}
__device__ __forceinline__ void cpasync16(unsigned dst, const float* src){
    asm volatile("cp.async.ca.shared.global [%0], [%1], 16;"::"r"(dst),"l"(src));
}
__device__ __forceinline__ void cpcommit(){ asm volatile("cp.async.commit_group;"::); }
__device__ __forceinline__ void sts_zero16(unsigned dst){
    asm volatile("st.shared.v4.b32 [%0], {%1,%1,%1,%1};"::"r"(dst),"r"(0):"memory");
}

// shared-memory GEMM chunk: acc += Ash[k][4rt..4rt+3] * Bsh[k][colBase..colBase+15]
__device__ __forceinline__ void gemm_chunk(const float* __restrict__ Ash, const float* __restrict__ Bsh,
                                           int klen, int rt, int colBase, ull acc[4][8]){
    #pragma unroll 4
    for (int k=0;k<klen;k++){
        float4 a4 = *reinterpret_cast<const float4*>(Ash + k*132 + (rt<<2));
        ull ap0=pack2(a4.x,a4.x), ap1=pack2(a4.y,a4.y), ap2=pack2(a4.z,a4.z), ap3=pack2(a4.w,a4.w);
        const ulonglong2* bp = reinterpret_cast<const ulonglong2*>(Bsh + k*128 + colBase);
        ulonglong2 b01=bp[0], b23=bp[1], b45=bp[2], b67=bp[3];
        ull bb[8] = {b01.x,b01.y,b23.x,b23.y,b45.x,b45.y,b67.x,b67.y};
        #pragma unroll
        for (int j=0;j<8;j++){
            fma2(acc[0][j],ap0,bb[j]); fma2(acc[1][j],ap1,bb[j]);
            fma2(acc[2][j],ap2,bb[j]); fma2(acc[3][j],ap3,bb[j]);
        }
    }
}

// ---------- K0: residual init ----------
__global__ void init_out_kernel(const float* __restrict__ xs, const float* __restrict__ xe, float* __restrict__ out){
    size_t i = (size_t)blockIdx.x*blockDim.x + threadIdx.x;
    size_t ns = (size_t)NN*120, ne = (size_t)NN*240;
    if (i < ns) out[i] = xs[i];
    if (i < ne) out[ns + i] = xe[i];
}

// ---------- K1: node LayerNorm + O3 LayerNorm ----------
__global__ void node_norm_kernel(const float* __restrict__ xs_in, const float* __restrict__ xe_in,
                                 const float* __restrict__ lnw, const float* __restrict__ lnb,
                                 const float* __restrict__ o3w){
    int lane = threadIdx.x & 31;
    int node = blockIdx.x*4 + (threadIdx.x >> 5);
    if (node >= NN) return;
    const float* xs = xs_in + (size_t)node*120;
    float v0=xs[lane], v1=xs[lane+32], v2=xs[lane+64], v3=(lane<24)?xs[lane+96]:0.f;
    float s = wsum(v0+v1+v2+v3);
    float q = wsum(v0*v0+v1*v1+v2*v2+v3*v3);
    float mean = s*(1.f/120.f);
    float inv = rsqrtf(q*(1.f/120.f) - mean*mean + 1e-5f);
    float* ns = g_ns + (size_t)node*120;
    ns[lane]    = (v0-mean)*inv*__ldg(lnw+lane)    + __ldg(lnb+lane);
    ns[lane+32] = (v1-mean)*inv*__ldg(lnw+lane+32) + __ldg(lnb+lane+32);
    ns[lane+64] = (v2-mean)*inv*__ldg(lnw+lane+64) + __ldg(lnb+lane+64);
    if (lane<24) ns[lane+96] = (v3-mean)*inv*__ldg(lnw+lane+96) + __ldg(lnb+lane+96);

    const float* xe = xe_in + (size_t)node*240;
    float* ne = g_ne + (size_t)node*240;
    {
        float e0=xe[lane], e1=xe[lane+32];
        float m = wsum(e0+e1)*(1.f/64.f);
        float c0=e0-m, c1=e1-m;
        float r = rsqrtf(wsum(c0*c0+c1*c1)*(1.f/64.f) + 1e-5f);
        ne[lane]    = c0*r*__ldg(o3w+lane);
        ne[lane+32] = c1*r*__ldg(o3w+lane+32);
    }
    {
        float y0=xe[64+lane], y1=xe[96+lane], y2=xe[128+lane];
        float r = rsqrtf(wsum(y0*y0+y1*y1+y2*y2)*(1.f/96.f) + 1e-5f);
        ne[64+lane]  = y0*r*__ldg(o3w+64+(lane)/3);
        ne[96+lane]  = y1*r*__ldg(o3w+64+(32+lane)/3);
        ne[128+lane] = y2*r*__ldg(o3w+64+(64+lane)/3);
    }
    {
        float z0=xe[160+lane], z1=xe[192+lane], z2=(lane<16)?xe[224+lane]:0.f;
        float r = rsqrtf(wsum(z0*z0+z1*z1+z2*z2)*(1.f/80.f) + 1e-5f);
        ne[160+lane] = z0*r*__ldg(o3w+96+(lane)/5);
        ne[192+lane] = z1*r*__ldg(o3w+96+(32+lane)/5);
        if (lane<16) ne[224+lane] = z2*r*__ldg(o3w+96+(64+lane)/5);
    }
}

// ---------- K2: all 6 projections in one launch, blockIdx.y selects weight ----------
__global__ __launch_bounds__(256) void proj_kernel(
    const float* __restrict__ W0, const float* __restrict__ W1, const float* __restrict__ W2,
    const float* __restrict__ W3, const float* __restrict__ W4, const float* __restrict__ W5)
{
    __shared__ alignas(16) float Bsh[32*128];
    __shared__ alignas(16) float Ash[32*132];
    int sel = blockIdx.y;
    const float* B = (sel==0)?W0:(sel==1)?W1:(sel==2)?W2:(sel==3)?W3:(sel==4)?W4:W5;
    float* C = (sel==0)?g_qinv:(sel==1)?g_kinv:(sel==2)?g_vinv:(sel==3)?g_qsph:(sel==4)?g_ksph:g_vsph;
    int ncols = (sel==5)?112:120;
    const float* A = g_ns;

    int tid = threadIdx.x;
    int ct = tid>>5, rt = tid&31;
    int rowBase = blockIdx.x*128, colBase = ct*16;
    ull acc[4][8];
    #pragma unroll
    for (int r=0;r<4;r++){
        #pragma unroll
        for (int j=0;j<8;j++) acc[r][j]=0ull;
    }
    for (int kc=0; kc<120; kc+=32){
        int klen = min(32, 120-kc);
        __syncthreads();
        for (int idx=tid; idx<klen*128; idx+=256){
            int k = idx>>7, j = idx&127;
            Bsh[idx] = (j<ncols) ? __ldg(B + (kc+k)*ncols + j) : 0.f;
        }
        for (int idx=tid; idx<128*klen; idx+=256){
            int row=idx/klen, kk=idx-row*klen;
            Ash[kk*132+row] = A[(size_t)(rowBase+row)*120 + kc+kk];
        }
        __syncthreads();
        gemm_chunk(Ash, Bsh, klen, rt, colBase, acc);
    }
    #pragma unroll
    for (int r=0;r<4;r++){
        int row = rowBase + rt*4 + r;
        #pragma unroll
        for (int j=0;j<8;j++){
            float lo,hi; unpack2(acc[r][j],lo,hi);
            int c0 = colBase + 2*j;
            if (c0   < ncols) C[(size_t)row*ncols + c0]   = lo;
            if (c0+1 < ncols) C[(size_t)row*ncols + c0+1] = hi;
        }
    }
}

// ---------- K3+K4+K5 fused mega edge kernel ----------
// smem layout (floats): hsh[240*132] | dsh[112*132] | bsh0[32*128] | bsh1[32*128]
//                       sb1[128] sb2[128] sb3[128] fc[128]
#define HS_OFF 0
#define DS_OFF 31680
#define B0_OFF 46464
#define B1_OFF 50560
#define SB1_OFF 54656
#define SB2_OFF 54784
#define SB3_OFF 54912
#define FC_OFF 55040
#define SMEM_FLOATS 55168

__global__ __launch_bounds__(256) void edge_mega_kernel(
    const int* __restrict__ ei, const float* __restrict__ rbf, const float* __restrict__ fcut,
    const float* __restrict__ inv_w1, const float* __restrict__ inv_b1,
    const float* __restrict__ inv_w2, const float* __restrict__ inv_b2,
    const float* __restrict__ rbf_w1, const float* __restrict__ rbf_b1,
    const float* __restrict__ rbf_w2, const float* __restrict__ rbf_b2)
{
    extern __shared__ float sm[];
    float* hsh = sm + HS_OFF;
    float* dsh = sm + DS_OFF;
    float* bsh[2] = { sm + B0_OFF, sm + B1_OFF };
    float* sb1 = sm + SB1_OFF;
    float* sb2 = sm + SB2_OFF;
    float* sb3 = sm + SB3_OFF;
    float* fc  = sm + FC_OFF;
    unsigned bsh_u32[2] = { smem_u32(bsh[0]), smem_u32(bsh[1]) };

    int tid = threadIdx.x;
    int warp = tid>>5, lane = tid&31;
    int ct = warp, rt = lane;
    int colBase = ct*16;
    int e0 = blockIdx.x * 128;

    // ---- phase 1: gather + equi_dot into dsh, rbf tile + rbf_w1 into bsh, biases, fcut ----
    for (int el = warp; el < 128; el += 8){
        int e = e0 + el;
        int a_n = __ldg(ei+EE+e), b_n = __ldg(ei+e);
        const float* a = g_ne + (size_t)a_n*240;
        const float* b = g_ne + (size_t)b_n*240;
        { float d = __ldg(a+lane)-__ldg(b+lane);       dsh[lane*132+el] = d*d; }
        { float d = __ldg(a+lane+32)-__ldg(b+lane+32); dsh[(lane+32)*132+el] = d*d; }
        { int base = 64 + lane*3; float s=0.f;
          #pragma unroll
          for (int j=0;j<3;j++){ float d=__ldg(a+base+j)-__ldg(b+base+j); s+=d*d; }
          dsh[(64+lane)*132+el] = s; }
        if (lane<16){ int base = 160 + lane*5; float s=0.f;
          #pragma unroll
          for (int j=0;j<5;j++){ float d=__ldg(a+base+j)-__ldg(b+base+j); s+=d*d; }
          dsh[(96+lane)*132+el] = s; }
    }
    // rbf tile (contiguous rows) transposed into bsh0 region
    float* rbf_sh  = bsh[0];
    float* rbfW_sh = bsh[1];
    for (int idx=tid; idx<128*20; idx+=256){
        int el = idx/20, k = idx - el*20;
        rbf_sh[k*132+el] = __ldg(rbf + (size_t)e0*20 + idx);
    }
    for (int idx=tid; idx<20*128; idx+=256){
        int k = idx>>7, j = idx&127;
        rbfW_sh[idx] = (j<120) ? __ldg(rbf_w1 + k*120 + j) : 0.f;
    }
    if (tid < 128){
        sb1[tid] = (tid<120) ? __ldg(rbf_b1+tid) : 0.f;
        sb2[tid] = (tid<120) ? __ldg(inv_b1+tid) : 0.f;
        sb3[tid] = (tid<120) ? (__ldg(inv_b2+tid)+__ldg(rbf_b2+tid)) : 0.f;
        fc[tid]  = __ldg(fcut + e0 + tid);
    }
    __syncthreads();

    ull acc[4][8];

    // ---- phase 2: h[:,120:240] = silu(rbf @ rbf_w1 + b) ----
    #pragma unroll
    for (int r=0;r<4;r++){
        #pragma unroll
        for (int j=0;j<8;j++) acc[r][j]=0ull;
    }
    gemm_chunk(rbf_sh, rbfW_sh, 20, rt, colBase, acc);
    #pragma unroll
    for (int r=0;r<4;r++){
        int row = rt*4 + r;
        #pragma unroll
        for (int j=0;j<8;j++){
            float lo,hi; unpack2(acc[r][j],lo,hi);
            int c0 = colBase + 2*j;
            if (c0 < 120){ float x = lo + sb1[c0];   hsh[(120+c0)*132 + row] = x/(1.f+__expf(-x)); }
            if (c0+1 < 120){ float x = hi + sb1[c0+1]; hsh[(121+c0)*132 + row] = x/(1.f+__expf(-x)); }
        }
    }
    __syncthreads();   // rbf_sh/rbfW_sh reads done; bsh now reusable for cp.async

    // ---- phase 3: h[:,0:120] = silu(d @ inv_w1 + b), K=112 in chunks of 32 ----
    {
        #pragma unroll
        for (int r=0;r<4;r++){
            #pragma unroll
            for (int j=0;j<8;j++) acc[r][j]=0ull;
        }
        const int NCH = 4; // 32,32,32,16
        // preload chunk 0
        {
            int klen = 32;
            for (int idx=tid; idx<klen*32; idx+=256){
                int kk = idx>>5, j4 = idx&31;
                unsigned dst = bsh_u32[0] + (unsigned)(kk*128 + j4*4)*4u;
                if (j4 < 30) cpasync16(dst, inv_w1 + (size_t)kk*120 + j4*4);
                else sts_zero16(dst);
            }
            cpcommit();
        }
        for (int c=0; c<NCH; c++){
            int kc = c*32;
            int klen = min(32, 112-kc);
            if (c+1 < NCH){
                int kc2 = (c+1)*32;
                int klen2 = min(32, 112-kc2);
                for (int idx=tid; idx<klen2*32; idx+=256){
                    int kk = idx>>5, j4 = idx&31;
                    unsigned dst = bsh_u32[(c+1)&1] + (unsigned)(kk*128 + j4*4)*4u;
                    if (j4 < 30) cpasync16(dst, inv_w1 + (size_t)(kc2+kk)*120 + j4*4);
                    else sts_zero16(dst);
                }
                cpcommit();
                asm volatile("cp.async.wait_group 1;"::);
            } else {
                asm volatile("cp.async.wait_group 0;"::);
            }
            __syncthreads();
            gemm_chunk(dsh + kc*132, bsh[c&1], klen, rt, colBase, acc);
            __syncthreads();
        }
        #pragma unroll
        for (int r=0;r<4;r++){
            int row = rt*4 + r;
            #pragma unroll
            for (int j=0;j<8;j++){
                float lo,hi; unpack2(acc[r][j],lo,hi);
                int c0 = colBase + 2*j;
                if (c0 < 120){ float x = lo + sb2[c0];   hsh[c0*132 + row] = x/(1.f+__expf(-x)); }
                if (c0+1 < 120){ float x = hi + sb2[c0+1]; hsh[(c0+1)*132 + row] = x/(1.f+__expf(-x)); }
            }
        }
        __syncthreads();
    }

    // ---- phase 4: w = (h @ [inv_w2; rbf_w2] + b) * fcut, K=240 in chunks of 32 ----
    {
        #pragma unroll
        for (int r=0;r<4;r++){
            #pragma unroll
            for (int j=0;j<8;j++) acc[r][j]=0ull;
        }
        const int NCH = 8; // 7x32 + 16
        {
            int klen = 32;
            for (int idx=tid; idx<klen*32; idx+=256){
                int kk = idx>>5, j4 = idx&31;
                unsigned dst = bsh_u32[0] + (unsigned)(kk*128 + j4*4)*4u;
                if (j4 < 30) cpasync16(dst, inv_w2 + (size_t)kk*120 + j4*4);
                else sts_zero16(dst);
            }
            cpcommit();
        }
        for (int c=0; c<NCH; c++){
            int kc = c*32;
            int klen = min(32, 240-kc);
            if (c+1 < NCH){
                int kc2 = (c+1)*32;
                int klen2 = min(32, 240-kc2);
                for (int idx=tid; idx<klen2*32; idx+=256){
                    int kk = idx>>5, j4 = idx&31;
                    unsigned dst = bsh_u32[(c+1)&1] + (unsigned)(kk*128 + j4*4)*4u;
                    if (j4 < 30){
                        int gk = kc2+kk;
                        const float* src = (gk<120) ? (inv_w2 + (size_t)gk*120 + j4*4)
                                                    : (rbf_w2 + (size_t)(gk-120)*120 + j4*4);
                        cpasync16(dst, src);
                    } else sts_zero16(dst);
                }
                cpcommit();
                asm volatile("cp.async.wait_group 1;"::);
            } else {
                asm volatile("cp.async.wait_group 0;"::);
            }
            __syncthreads();
            gemm_chunk(hsh + kc*132, bsh[c&1], klen, rt, colBase, acc);
            __syncthreads();
        }
        #pragma unroll
        for (int r=0;r<4;r++){
            int row = rt*4 + r;
            float f = fc[row];
            #pragma unroll
            for (int j=0;j<8;j++){
                float lo,hi; unpack2(acc[r][j],lo,hi);
                int c0 = colBase + 2*j;
                if (c0 < 120)   g_w[(size_t)(e0+row)*120 + c0]   = (lo + sb3[c0])*f;
                if (c0+1 < 120) g_w[(size_t)(e0+row)*120 + c0+1] = (hi + sb3[c0+1])*f;
            }
        }
    }
}

// ---------- K6: attention + gated messages + scatter ----------
__global__ __launch_bounds__(256) void edge_attn_kernel(const int* __restrict__ ei,
                                                        const float* __restrict__ fcut,
                                                        const float* __restrict__ rsh,
                                                        float* __restrict__ outS,
                                                        float* __restrict__ outE){
    __shared__ float sgate[8][116];
    int warp = threadIdx.x>>5, lane = threadIdx.x&31;
    int e = blockIdx.x*8 + warp;
    int ct = __ldg(ei+e), nb = __ldg(ei+EE+e);
    float fc = __ldg(fcut+e);
    const float* w  = g_w   + (size_t)e*120;
    const float* qi = g_qinv + (size_t)ct*120;
    const float* ki = g_kinv + (size_t)nb*120;
    const float* vi = g_vinv + (size_t)nb*120;
    const float* qs = g_qsph + (size_t)ct*120;
    const float* ks = g_ksph + (size_t)nb*120;
    const float* vs = g_vsph + (size_t)nb*112;

    float s0=0,s1=0,s2=0,s3=0,t0=0,t1=0,t2=0;
    if (lane < 30){
        float4 wv = ldg4(w + 4*lane);
        float4 q  = ldg4(qi + 4*lane), k = ldg4(ki + 4*lane);
        float4 qe = ldg4(qs + 4*lane), ke = ldg4(ks + 4*lane);
        float wa[4]={wv.x,wv.y,wv.z,wv.w};
        float pa[4]={q.x*k.x, q.y*k.y, q.z*k.z, q.w*k.w};
        float pe[4]={qe.x*ke.x, qe.y*ke.y, qe.z*ke.z, qe.w*ke.w};
        #pragma unroll
        for (int j=0;j<4;j++){
            int idx = 4*lane + j;
            float p = wa[j]*pa[j];
            float pq = wa[j]*pe[j];
            int h = idx/30, l = idx/40;
            s0 += (h==0)?p:0.f; s1 += (h==1)?p:0.f; s2 += (h==2)?p:0.f; s3 += (h==3)?p:0.f;
            t0 += (l==0)?pq:0.f; t1 += (l==1)?pq:0.f; t2 += (l==2)?pq:0.f;
        }
    }
    const float SC_S = 0.091287092917527686f;   // 1/sqrt(120)
    const float SC_E = 0.094491118252306805f;   // 1/sqrt(112)
    s0 = wsum(s0)*SC_S; s1 = wsum(s1)*SC_S; s2 = wsum(s2)*SC_S; s3 = wsum(s3)*SC_S;
    t0 = wsum(t0)*SC_E; t1 = wsum(t1)*SC_E; t2 = wsum(t2)*SC_E;

    if (lane < 30){
        float4 v = ldg4(vi + 4*lane);
        float va[4]={v.x,v.y,v.z,v.w}, m[4];
        #pragma unroll
        for (int j=0;j<4;j++){
            int h = (4*lane+j)/30;
            float ss = (h==0)?s0:((h==1)?s1:((h==2)?s2:s3));
            m[j] = ss*va[j];
        }
        red4(outS + (size_t)ct*120 + 4*lane, m[0],m[1],m[2],m[3]);
    }
    if (lane < 28){
        float4 v = ldg4(vs + 4*lane);
        float va[4]={v.x,v.y,v.z,v.w};
        #pragma unroll
        for (int j=0;j<4;j++){
            int ir = 4*lane + j;
            float tl = (ir<64)?t0:((ir<96)?t1:t2);
            sgate[warp][ir] = tl*va[j]*fc;
        }
    }
    __syncwarp();
    if (lane < 30){
        int base = 8*lane;
        float4 r0 = ldg4(rsh + (size_t)e*240 + base);
        float4 r1 = ldg4(rsh + (size_t)e*240 + base + 4);
        float ra[8]={r0.x,r0.y,r0.z,r0.w,r1.x,r1.y,r1.z,r1.w}, m[8];
        #pragma unroll
        for (int j=0;j<8;j++){
            int c = base + j;
            int ir = (c<64)? c : (c<160)? 64+(c-64)/3 : 96+(c-160)/5;
            m[j] = ra[j]*sgate[warp][ir];
        }
        red4(outE + (size_t)ct*240 + base,     m[0],m[1],m[2],m[3]);
        red4(outE + (size_t)ct*240 + base + 4, m[4],m[5],m[6],m[7]);
    }
}

extern "C" void kernel_launch(void* const* d_in, const int* in_sizes, int n_in,
                              void* d_out, int out_size){
    const float* node_scalar=(const float*)d_in[0];
    const float* node_equi  =(const float*)d_in[1];
    const float* rbf        =(const float*)d_in[2];
    const float* fcut       =(const float*)d_in[3];
    const float* rsh        =(const float*)d_in[4];
    const float* ln_w =(const float*)d_in[5];
    const float* ln_b =(const float*)d_in[6];
    const float* o3w  =(const float*)d_in[7];
    const float* Wq   =(const float*)d_in[8];
    const float* Wk   =(const float*)d_in[9];
    const float* Wv   =(const float*)d_in[10];
    const float* Wqs  =(const float*)d_in[11];
    const float* Wks  =(const float*)d_in[12];
    const float* Wvs  =(const float*)d_in[13];
    const float* rbf_w1=(const float*)d_in[14];
    const float* rbf_b1=(const float*)d_in[15];
    const float* rbf_w2=(const float*)d_in[16];
    const float* rbf_b2=(const float*)d_in[17];
    const float* inv_w1=(const float*)d_in[18];
    const float* inv_b1=(const float*)d_in[19];
    const float* inv_w2=(const float*)d_in[20];
    const float* inv_b2=(const float*)d_in[21];
    const int*   ei    =(const int*)d_in[22];

    float* outS = (float*)d_out;
    float* outE = outS + (size_t)NN*120;

    static int smem_set = 0;
    if (!smem_set){
        cudaFuncSetAttribute(edge_mega_kernel, cudaFuncAttributeMaxDynamicSharedMemorySize, SMEM_FLOATS*4);
        smem_set = 1;
    }

    init_out_kernel<<<(NN*240 + 255)/256, 256>>>(node_scalar, node_equi, (float*)d_out);
    node_norm_kernel<<<NN/4, 128>>>(node_scalar, node_equi, ln_w, ln_b, o3w);
    proj_kernel<<<dim3(NN/128, 6), 256>>>(Wq, Wk, Wv, Wqs, Wks, Wvs);
    edge_mega_kernel<<<EE/128, 256, SMEM_FLOATS*4>>>(ei, rbf, fcut,
        inv_w1, inv_b1, inv_w2, inv_b2, rbf_w1, rbf_b1, rbf_w2, rbf_b2);
    edge_attn_kernel<<<EE/8, 256>>>(ei, fcut, rsh, outS, outE);
}